// round 7
// baseline (speedup 1.0000x reference)
#include <cuda_runtime.h>
#include <cuda_fp16.h>
#include <cstdint>

#define MMV 2048
#define NNV 4096
#define KKV 4096

// fp16(x), k-permuted (0,4,1,5,2,6,3,7) within each aligned 8-k block
__device__ __align__(16) __half g_xh[(size_t)MMV * KKV];

// ---------------------------------------------------------------------------
// asm helpers
// ---------------------------------------------------------------------------
__device__ __forceinline__ void ldsm4(uint32_t* r, uint32_t addr) {
    asm volatile("ldmatrix.sync.aligned.m8n8.x4.shared.b16 {%0,%1,%2,%3}, [%4];"
                 : "=r"(r[0]), "=r"(r[1]), "=r"(r[2]), "=r"(r[3]) : "r"(addr));
}
__device__ __forceinline__ void mma_f16(float* c, const uint32_t* a, const uint32_t* b) {
    asm volatile("mma.sync.aligned.m16n8k16.row.col.f32.f16.f16.f32 "
                 "{%0,%1,%2,%3}, {%4,%5,%6,%7}, {%8,%9}, {%0,%1,%2,%3};"
                 : "+f"(c[0]), "+f"(c[1]), "+f"(c[2]), "+f"(c[3])
                 : "r"(a[0]), "r"(a[1]), "r"(a[2]), "r"(a[3]), "r"(b[0]), "r"(b[1]));
}
__device__ __forceinline__ void cpa16(uint32_t s, const void* g) {
    asm volatile("cp.async.cg.shared.global [%0], [%1], 16;" :: "r"(s), "l"(g));
}
#define CP_COMMIT() asm volatile("cp.async.commit_group;" ::: "memory")
#define CP_WAIT2()  asm volatile("cp.async.wait_group 2;" ::: "memory")

// ---------------------------------------------------------------------------
// Prep: x -> fp16 with intra-8 k-permutation (0,4,1,5,2,6,3,7)
// thread handles one 8-k block
// ---------------------------------------------------------------------------
__global__ void split_x_kernel(const float4* __restrict__ x4) {
    size_t i = (size_t)blockIdx.x * blockDim.x + threadIdx.x;   // 8-block index
    float4 a = x4[2 * i], b = x4[2 * i + 1];
    __half2 p0 = __floats2half2_rn(a.x, b.x);   // (f0, f4)
    __half2 p1 = __floats2half2_rn(a.y, b.y);   // (f1, f5)
    __half2 p2 = __floats2half2_rn(a.z, b.z);   // (f2, f6)
    __half2 p3 = __floats2half2_rn(a.w, b.w);   // (f3, f7)
    uint4 o;
    o.x = *(uint32_t*)&p0; o.y = *(uint32_t*)&p1;
    o.z = *(uint32_t*)&p2; o.w = *(uint32_t*)&p3;
    ((uint4*)g_xh)[i] = o;
}

// ---------------------------------------------------------------------------
// GEMM: C = xh @ Wint with per-group fp32 scale fold, + bias.
// In-GEMM B dequant: LDG packed int32 -> magic extract -> exact (w-z) fp16
// -> STS.128 into [n][k] smem rows (swizzled). A via cp.async (4-stage).
// CTA 128x128, BK=64, 8 warps (4m x 2n), warp tile 32x64.
// ---------------------------------------------------------------------------
#define NS 4
#define STG_BYTES 32768          // A 16K | B 16K
#define SM_TBL 24576             // s_sc 16K fp32 + zt 8K half
#define SMEM_TOTAL (SM_TBL + NS * STG_BYTES)   // 155648

__global__ void __launch_bounds__(256, 1)
gemm_kernel(const float* __restrict__ scales,
            const float* __restrict__ zp,
            const int*   __restrict__ qw,
            const float* __restrict__ bias,
            float* __restrict__ C)
{
    extern __shared__ __align__(16) char smem[];
    const uint32_t sb = (uint32_t)__cvta_generic_to_shared(smem);
    const int tid = threadIdx.x, lane = tid & 31, wid = tid >> 5;
    const int wm = wid & 3, wn = wid >> 2;
    const int m0 = blockIdx.y * 128, n0 = blockIdx.x * 128;

    // ---- tables: clipped scales (fp32) and 1024+z (fp16) ----
    float*  s_sc = (float*)smem;
    __half* zt   = (__half*)(smem + 16384);
    for (int i = tid; i < 4096; i += 256) {
        int g = i >> 7, j = i & 127;
        float s = scales[g * NNV + n0 + j];
        s_sc[i] = fminf(fmaxf(s, 1e-5f), 1e4f);
        float z = fminf(fmaxf(rintf(zp[g * NNV + n0 + j]), 0.0f), 15.0f);
        zt[i] = __float2half_rn(1024.0f + z);
    }

    // ---- B producer thread mapping ----
    const int bn      = ((wid & 3) * 32) + lane;   // 0..127 (n within tile)
    const int kphalf  = wid >> 2;                   // 0/1 -> kp 0-3 or 4-7

    // A loader (cp.async), 4 x 16B chunks per thread
    auto load_A = [&](int kt, int st) {
        uint32_t base = sb + SM_TBL + st * STG_BYTES;
#pragma unroll
        for (int j = 0; j < 4; ++j) {
            int q = tid + j * 256;
            int r = q >> 3, c = q & 7;
            uint32_t so = base + (uint32_t)(r * 8 + (c ^ (r & 7))) * 16;
            cpa16(so, g_xh + (size_t)(m0 + r) * KKV + kt * 64 + c * 8);
        }
    };
    // B LDG into registers for stage kt
    uint32_t rb[2][4];
    auto ldg_B = [&](int kt, int buf) {
#pragma unroll
        for (int j = 0; j < 4; ++j)
            rb[buf][j] = (uint32_t)__ldg(qw + (size_t)(kt * 8 + kphalf * 4 + j) * NNV + n0 + bn);
    };
    // B dequant + STS for stage kt from register buffer
    auto sts_B = [&](int kt, int buf) {
        int g = kt >> 1;
        __half2 z2 = __half2half2(zt[g * 128 + bn]);
        uint32_t base = sb + SM_TBL + (kt & 3) * STG_BYTES + 16384;
        uint32_t rowo = base + (uint32_t)bn * 128;
#pragma unroll
        for (int j = 0; j < 4; ++j) {
            int c = kphalf * 4 + j;
            uint32_t q = rb[buf][j];
            uint32_t t0 = (q & 0x000F000Fu) | 0x64006400u;
            uint32_t t1 = ((q >> 4)  & 0x000F000Fu) | 0x64006400u;
            uint32_t t2 = ((q >> 8)  & 0x000F000Fu) | 0x64006400u;
            uint32_t t3 = ((q >> 12) & 0x000F000Fu) | 0x64006400u;
            __half2 w0 = __hsub2(*(__half2*)&t0, z2);
            __half2 w1 = __hsub2(*(__half2*)&t1, z2);
            __half2 w2 = __hsub2(*(__half2*)&t2, z2);
            __half2 w3 = __hsub2(*(__half2*)&t3, z2);
            uint4 o;
            o.x = *(uint32_t*)&w0; o.y = *(uint32_t*)&w1;
            o.z = *(uint32_t*)&w2; o.w = *(uint32_t*)&w3;
            uint32_t ad = rowo + (uint32_t)((c ^ (bn & 7)) * 16);
            asm volatile("st.shared.v4.b32 [%0], {%1,%2,%3,%4};"
                         :: "r"(ad), "r"(o.x), "r"(o.y), "r"(o.z), "r"(o.w) : "memory");
        }
    };

    // ---- prologue ----
    ldg_B(0, 0);
    ldg_B(1, 1);
    load_A(0, 0); CP_COMMIT();
    load_A(1, 1); CP_COMMIT();
    load_A(2, 2); CP_COMMIT();
    __syncthreads();            // tables visible
    sts_B(0, 0);                // stage0 B into smem (rb[0] now free)

    // ---- ldmatrix address precompute ----
    const int lane_r = lane & 15, chh = lane >> 4;
    uint32_t arow[2], axr[2];
#pragma unroll
    for (int t = 0; t < 2; ++t) {
        int r = wm * 32 + t * 16 + lane_r;
        arow[t] = (uint32_t)r * 128;
        axr[t]  = (uint32_t)(r & 7);
    }
    // B: lanes 0-7/8-15/16-23/24-31 -> (ngrp0,c0)(ngrp0,c1)(ngrp1,c0)(ngrp1,c1)
    const uint32_t bl7   = lane & 7;
    const uint32_t bngh  = (lane >> 4) & 1;
    const uint32_t bch   = (lane >> 3) & 1;
    const uint32_t brow  = (uint32_t)(wn * 64 + bngh * 8 + bl7) * 128;
    const uint32_t bcx   = bch ^ bl7;

    float accG[2][8][4];
    float accM[2][8][4];
#pragma unroll
    for (int t = 0; t < 2; ++t)
#pragma unroll
        for (int nt = 0; nt < 8; ++nt)
#pragma unroll
            for (int i = 0; i < 4; ++i) { accG[t][nt][i] = 0.f; accM[t][nt][i] = 0.f; }

    for (int kt = 0; kt < 64; ++kt) {
        CP_WAIT2();
        __syncthreads();

        const int st = kt & 3;
        const uint32_t Ab = sb + SM_TBL + st * STG_BYTES;
        const uint32_t Bb = Ab + 16384;

        // producers for upcoming stages
        if (kt + 1 < 64) sts_B(kt + 1, (kt + 1) & 1);
        if (kt + 2 < 64) ldg_B(kt + 2, kt & 1);
        if (kt + 3 < 64) load_A(kt + 3, (kt + 3) & 3);
        CP_COMMIT();

#pragma unroll
        for (int ks = 0; ks < 4; ++ks) {
            uint32_t af[2][4], bfr[4][4];
#pragma unroll
            for (int t = 0; t < 2; ++t) {
                uint32_t co = ((uint32_t)(ks * 2 + chh) ^ axr[t]) * 16;
                ldsm4(af[t], Ab + arow[t] + co);
            }
#pragma unroll
            for (int p = 0; p < 4; ++p) {
                uint32_t ad = Bb + brow + (uint32_t)p * 2048
                            + (uint32_t)(((2 * ks) ^ bcx) * 16);
                ldsm4(bfr[p], ad);
            }
#pragma unroll
            for (int t = 0; t < 2; ++t)
#pragma unroll
                for (int nt = 0; nt < 8; ++nt)
                    mma_f16(accG[t][nt], af[t], &bfr[nt >> 1][(nt & 1) * 2]);
        }

        if (kt & 1) {   // end of 128-K group: fold with scales
            const int g = kt >> 1;
            const float* sg = s_sc + g * 128 + wn * 64 + (lane & 3) * 2;
#pragma unroll
            for (int nt = 0; nt < 8; ++nt) {
                float2 sv = *(const float2*)(sg + nt * 8);
#pragma unroll
                for (int t = 0; t < 2; ++t) {
                    accM[t][nt][0] += sv.x * accG[t][nt][0];
                    accM[t][nt][1] += sv.y * accG[t][nt][1];
                    accM[t][nt][2] += sv.x * accG[t][nt][2];
                    accM[t][nt][3] += sv.y * accG[t][nt][3];
                    accG[t][nt][0] = 0.f; accG[t][nt][1] = 0.f;
                    accG[t][nt][2] = 0.f; accG[t][nt][3] = 0.f;
                }
            }
        }
    }

    // epilogue
#pragma unroll
    for (int t = 0; t < 2; ++t) {
        int row0 = m0 + wm * 32 + t * 16 + (lane >> 2);
#pragma unroll
        for (int nt = 0; nt < 8; ++nt) {
            int col = n0 + wn * 64 + nt * 8 + (lane & 3) * 2;
            float2 b = *(const float2*)(bias + col);
            float2 o0, o1;
            o0.x = accM[t][nt][0] + b.x;  o0.y = accM[t][nt][1] + b.y;
            o1.x = accM[t][nt][2] + b.x;  o1.y = accM[t][nt][3] + b.y;
            *(float2*)(C + (size_t)row0 * NNV + col)       = o0;
            *(float2*)(C + (size_t)(row0 + 8) * NNV + col) = o1;
        }
    }
}

// ---------------------------------------------------------------------------
// Host. Inputs: x, scales, zero_points, bias, qweight
// ---------------------------------------------------------------------------
extern "C" void kernel_launch(void* const* d_in, const int* in_sizes, int n_in,
                              void* d_out, int out_size)
{
    const float* x      = (const float*)d_in[0];
    const float* scales = (const float*)d_in[1];
    const float* zp     = (const float*)d_in[2];
    const float* bias   = (const float*)d_in[3];
    const int*   qw     = (const int*)d_in[4];
    float*       out    = (float*)d_out;

    split_x_kernel<<<(MMV * KKV / 8) / 256, 256>>>((const float4*)x);

    static bool attr_set = false;
    if (!attr_set) {
        cudaFuncSetAttribute(gemm_kernel, cudaFuncAttributeMaxDynamicSharedMemorySize, SMEM_TOTAL);
        attr_set = true;
    }
    gemm_kernel<<<dim3(NNV / 128, MMV / 128), 256, SMEM_TOTAL>>>(scales, zp, qw, bias, out);
}

// round 8
// speedup vs baseline: 1.6523x; 1.6523x over previous
#include <cuda_runtime.h>
#include <cuda_fp16.h>
#include <cstdint>

#define MMV 2048
#define NNV 4096
#define KKV 4096

// Scratch (__device__ globals; no allocations allowed)
__device__ __align__(16) __half g_xh[(size_t)MMV * KKV];  // fp16(x)
__device__ __align__(16) __half g_wi[(size_t)KKV * NNV];  // (q - z) exact integer, [K][N]

// ---------------------------------------------------------------------------
// asm helpers
// ---------------------------------------------------------------------------
__device__ __forceinline__ void ldsm4(uint32_t* r, uint32_t addr) {
    asm volatile("ldmatrix.sync.aligned.m8n8.x4.shared.b16 {%0,%1,%2,%3}, [%4];"
                 : "=r"(r[0]), "=r"(r[1]), "=r"(r[2]), "=r"(r[3]) : "r"(addr));
}
__device__ __forceinline__ void ldsm4t(uint32_t* r, uint32_t addr) {
    asm volatile("ldmatrix.sync.aligned.m8n8.x4.trans.shared.b16 {%0,%1,%2,%3}, [%4];"
                 : "=r"(r[0]), "=r"(r[1]), "=r"(r[2]), "=r"(r[3]) : "r"(addr));
}
__device__ __forceinline__ void mma_f16(float* c, const uint32_t* a, const uint32_t* b) {
    asm volatile("mma.sync.aligned.m16n8k16.row.col.f32.f16.f16.f32 "
                 "{%0,%1,%2,%3}, {%4,%5,%6,%7}, {%8,%9}, {%0,%1,%2,%3};"
                 : "+f"(c[0]), "+f"(c[1]), "+f"(c[2]), "+f"(c[3])
                 : "r"(a[0]), "r"(a[1]), "r"(a[2]), "r"(a[3]), "r"(b[0]), "r"(b[1]));
}
__device__ __forceinline__ void cpa16(uint32_t s, const void* g) {
    asm volatile("cp.async.cg.shared.global [%0], [%1], 16;" :: "r"(s), "l"(g));
}
#define CP_COMMIT() asm volatile("cp.async.commit_group;" ::: "memory")
#define CP_WAIT2()  asm volatile("cp.async.wait_group 2;" ::: "memory")

// ---------------------------------------------------------------------------
// Fused prep: blocks [0,8192) convert x -> fp16; blocks [8192,16384) unpack W.
// ---------------------------------------------------------------------------
__global__ void prep_kernel(const float4* __restrict__ x4,
                            const int* __restrict__ qw,
                            const float* __restrict__ zp)
{
    if (blockIdx.x < 8192) {
        size_t i = (size_t)blockIdx.x * blockDim.x + threadIdx.x;   // over M*K/4
        float4 v = x4[i];
        __align__(8) __half h[4];
        h[0] = __float2half_rn(v.x); h[1] = __float2half_rn(v.y);
        h[2] = __float2half_rn(v.z); h[3] = __float2half_rn(v.w);
        ((uint2*)g_xh)[i] = *(uint2*)h;
    } else {
        int T = (blockIdx.x - 8192) * blockDim.x + threadIdx.x;     // over (K/8)*N
        int n  = T & (NNV - 1);
        int kp = T >> 12;
        int g  = kp >> 4;
        float z = fminf(fmaxf(rintf(zp[g * NNV + n]), 0.0f), 15.0f);
        int q = qw[(size_t)kp * NNV + n];
#pragma unroll
        for (int j = 0; j < 8; ++j) {
            int w = (q >> (4 * j)) & 15;
            g_wi[(size_t)(kp * 8 + j) * NNV + n] = __float2half_rn((float)w - z);
        }
    }
}

// ---------------------------------------------------------------------------
// GEMM: C = xh @ Wint with per-group fp32 scale fold, + bias
// CTA tile 64x128, BK=64, 4 warps (2m x 2n), warp tile 32x64 (same microkernel
// as the proven 274us version). 2 CTAs/SM -> grid 1024 over 296 slots = 98.9%
// wave utilization (vs 86.5% at grid 512 / 1 CTA/SM).
// smem: [0,16K) scales; NS=4 stages x (A 8K | B 16K)
// ---------------------------------------------------------------------------
#define NS 4
#define STG_BYTES 24576
#define SM_TBL 16384
#define SMEM_TOTAL (SM_TBL + NS * STG_BYTES)   // 114688

__global__ void __launch_bounds__(128, 2)
gemm_kernel(const float* __restrict__ scales,
            const float* __restrict__ bias,
            float* __restrict__ C)
{
    extern __shared__ __align__(16) char smem[];
    const uint32_t sb = (uint32_t)__cvta_generic_to_shared(smem);
    const int tid = threadIdx.x, lane = tid & 31, wid = tid >> 5;
    const int wm = wid & 1, wn = wid >> 1;
    const int m0 = blockIdx.y * 64, n0 = blockIdx.x * 128;

    // stage clipped scales [32 groups][128 cols]
    float* s_sc = (float*)smem;
    for (int i = tid; i < 4096; i += 128) {
        int g = i >> 7, j = i & 127;
        float s = scales[g * NNV + n0 + j];
        s_sc[i] = fminf(fmaxf(s, 1e-5f), 1e4f);
    }

    // loader: A 64x64 fp16 (512 x 16B chunks), B 64x128 fp16 (1024 chunks)
    auto load_stage = [&](int kt, int st) {
        uint32_t base = sb + SM_TBL + st * STG_BYTES;
#pragma unroll
        for (int j = 0; j < 4; ++j) {
            int q = tid + j * 128;
            int r = q >> 3, c = q & 7;
            uint32_t so = base + (uint32_t)(r * 8 + (c ^ (r & 7))) * 16;
            cpa16(so, g_xh + (size_t)(m0 + r) * KKV + kt * 64 + c * 8);
        }
#pragma unroll
        for (int j = 0; j < 8; ++j) {
            int q = tid + j * 128;
            int r = q >> 4, c = q & 15;
            uint32_t so = base + 8192 + (uint32_t)(r * 16 + (c ^ (r & 7))) * 16;
            cpa16(so, g_wi + (size_t)(kt * 64 + r) * NNV + n0 + c * 8);
        }
    };

    // prefill NS-1 = 3 stages
#pragma unroll
    for (int s = 0; s < NS - 1; ++s) { load_stage(s, s); CP_COMMIT(); }

    // ldmatrix address precompute
    const int lane_r = lane & 15, chh = lane >> 4;
    uint32_t arow[2], axr[2];
#pragma unroll
    for (int t = 0; t < 2; ++t) {
        int r = wm * 32 + t * 16 + lane_r;
        arow[t] = (uint32_t)r * 128;            // 128 B per A row
        axr[t]  = (uint32_t)(r & 7);
    }
    const uint32_t xb = (uint32_t)(lane_r & 7);
    uint32_t bcol[4];
#pragma unroll
    for (int bb = 0; bb < 4; ++bb)
        bcol[bb] = (uint32_t)(wn * 8 + (((uint32_t)(bb * 2 + chh)) ^ xb)) * 16;
    uint32_t boff[4];
#pragma unroll
    for (int ks = 0; ks < 4; ++ks)
        boff[ks] = (uint32_t)(ks * 16 + lane_r) * 256;   // 256 B per B row

    float accG[2][8][4];
    float accM[2][8][4];
#pragma unroll
    for (int t = 0; t < 2; ++t)
#pragma unroll
        for (int nt = 0; nt < 8; ++nt)
#pragma unroll
            for (int i = 0; i < 4; ++i) { accG[t][nt][i] = 0.f; accM[t][nt][i] = 0.f; }

    for (int kt = 0; kt < 64; ++kt) {
        CP_WAIT2();
        __syncthreads();

        const int st = kt & 3;
        const uint32_t Ab = sb + SM_TBL + st * STG_BYTES;
        const uint32_t Bb = Ab + 8192;

        // issue next loads into the slot freed last iteration
        if (kt + NS - 1 < 64) load_stage(kt + NS - 1, (kt + NS - 1) & 3);
        CP_COMMIT();

#pragma unroll
        for (int ks = 0; ks < 4; ++ks) {
            uint32_t af[2][4], bfr[4][4];
#pragma unroll
            for (int t = 0; t < 2; ++t) {
                uint32_t co = ((uint32_t)(ks * 2 + chh) ^ axr[t]) * 16;
                ldsm4(af[t], Ab + arow[t] + co);
            }
#pragma unroll
            for (int bb = 0; bb < 4; ++bb)
                ldsm4t(bfr[bb], Bb + boff[ks] + bcol[bb]);
#pragma unroll
            for (int t = 0; t < 2; ++t)
#pragma unroll
                for (int nt = 0; nt < 8; ++nt)
                    mma_f16(accG[t][nt], af[t], &bfr[nt >> 1][(nt & 1) * 2]);
        }

        if (kt & 1) {   // end of 128-K group: fold with scales
            const int g = kt >> 1;
            const float* sg = s_sc + g * 128 + wn * 64 + (lane & 3) * 2;
#pragma unroll
            for (int nt = 0; nt < 8; ++nt) {
                float2 sv = *(const float2*)(sg + nt * 8);
#pragma unroll
                for (int t = 0; t < 2; ++t) {
                    accM[t][nt][0] += sv.x * accG[t][nt][0];
                    accM[t][nt][1] += sv.y * accG[t][nt][1];
                    accM[t][nt][2] += sv.x * accG[t][nt][2];
                    accM[t][nt][3] += sv.y * accG[t][nt][3];
                    accG[t][nt][0] = 0.f; accG[t][nt][1] = 0.f;
                    accG[t][nt][2] = 0.f; accG[t][nt][3] = 0.f;
                }
            }
        }
    }

    // epilogue
#pragma unroll
    for (int t = 0; t < 2; ++t) {
        int row0 = m0 + wm * 32 + t * 16 + (lane >> 2);
#pragma unroll
        for (int nt = 0; nt < 8; ++nt) {
            int col = n0 + wn * 64 + nt * 8 + (lane & 3) * 2;
            float2 b = *(const float2*)(bias + col);
            float2 o0, o1;
            o0.x = accM[t][nt][0] + b.x;  o0.y = accM[t][nt][1] + b.y;
            o1.x = accM[t][nt][2] + b.x;  o1.y = accM[t][nt][3] + b.y;
            *(float2*)(C + (size_t)row0 * NNV + col)       = o0;
            *(float2*)(C + (size_t)(row0 + 8) * NNV + col) = o1;
        }
    }
}

// ---------------------------------------------------------------------------
// Host. Inputs: x, scales, zero_points, bias, qweight
// ---------------------------------------------------------------------------
extern "C" void kernel_launch(void* const* d_in, const int* in_sizes, int n_in,
                              void* d_out, int out_size)
{
    const float* x      = (const float*)d_in[0];
    const float* scales = (const float*)d_in[1];
    const float* zp     = (const float*)d_in[2];
    const float* bias   = (const float*)d_in[3];
    const int*   qw     = (const int*)d_in[4];
    float*       out    = (float*)d_out;

    prep_kernel<<<16384, 256>>>((const float4*)x, qw, zp);

    static bool attr_set = false;
    if (!attr_set) {
        cudaFuncSetAttribute(gemm_kernel, cudaFuncAttributeMaxDynamicSharedMemorySize, SMEM_TOTAL);
        attr_set = true;
    }
    gemm_kernel<<<dim3(NNV / 128, MMV / 64), 128, SMEM_TOTAL>>>(scales, bias, out);
}

// round 9
// speedup vs baseline: 1.8655x; 1.1290x over previous
#include <cuda_runtime.h>
#include <cuda_fp16.h>
#include <cstdint>

#define MMV 2048
#define NNV 4096
#define KKV 4096

// Scratch (__device__ globals; no allocations allowed)
__device__ __align__(16) __half g_xh[(size_t)MMV * KKV];  // fp16(x)
__device__ __align__(16) __half g_wd[(size_t)KKV * NNV];  // fp16(s*(q-z)), [K][N]

// ---------------------------------------------------------------------------
// asm helpers
// ---------------------------------------------------------------------------
__device__ __forceinline__ void ldsm4(uint32_t* r, uint32_t addr) {
    asm volatile("ldmatrix.sync.aligned.m8n8.x4.shared.b16 {%0,%1,%2,%3}, [%4];"
                 : "=r"(r[0]), "=r"(r[1]), "=r"(r[2]), "=r"(r[3]) : "r"(addr));
}
__device__ __forceinline__ void ldsm4t(uint32_t* r, uint32_t addr) {
    asm volatile("ldmatrix.sync.aligned.m8n8.x4.trans.shared.b16 {%0,%1,%2,%3}, [%4];"
                 : "=r"(r[0]), "=r"(r[1]), "=r"(r[2]), "=r"(r[3]) : "r"(addr));
}
__device__ __forceinline__ void mma_f16(float* c, const uint32_t* a, const uint32_t* b) {
    asm volatile("mma.sync.aligned.m16n8k16.row.col.f32.f16.f16.f32 "
                 "{%0,%1,%2,%3}, {%4,%5,%6,%7}, {%8,%9}, {%0,%1,%2,%3};"
                 : "+f"(c[0]), "+f"(c[1]), "+f"(c[2]), "+f"(c[3])
                 : "r"(a[0]), "r"(a[1]), "r"(a[2]), "r"(a[3]), "r"(b[0]), "r"(b[1]));
}
__device__ __forceinline__ void cpa16(uint32_t s, const void* g) {
    asm volatile("cp.async.cg.shared.global [%0], [%1], 16;" :: "r"(s), "l"(g));
}
#define CP_COMMIT() asm volatile("cp.async.commit_group;" ::: "memory")
#define CP_WAIT1()  asm volatile("cp.async.wait_group 1;" ::: "memory")

// ---------------------------------------------------------------------------
// Fused prep: blocks [0,8192) convert x -> fp16; blocks [8192,16384) unpack W
// to fp16( clip(s) * (q - clip(round(z),0,15)) ).
// ---------------------------------------------------------------------------
__global__ void prep_kernel(const float4* __restrict__ x4,
                            const int* __restrict__ qw,
                            const float* __restrict__ zp,
                            const float* __restrict__ scales)
{
    if (blockIdx.x < 8192) {
        size_t i = (size_t)blockIdx.x * blockDim.x + threadIdx.x;   // over M*K/4
        float4 v = x4[i];
        __align__(8) __half h[4];
        h[0] = __float2half_rn(v.x); h[1] = __float2half_rn(v.y);
        h[2] = __float2half_rn(v.z); h[3] = __float2half_rn(v.w);
        ((uint2*)g_xh)[i] = *(uint2*)h;
    } else {
        int T = (blockIdx.x - 8192) * blockDim.x + threadIdx.x;     // over (K/8)*N
        int n  = T & (NNV - 1);
        int kp = T >> 12;
        int g  = kp >> 4;
        float z = fminf(fmaxf(rintf(zp[g * NNV + n]), 0.0f), 15.0f);
        float s = fminf(fmaxf(scales[g * NNV + n], 1e-5f), 1e4f);
        int q = qw[(size_t)kp * NNV + n];
#pragma unroll
        for (int j = 0; j < 8; ++j) {
            int w = (q >> (4 * j)) & 15;
            g_wd[(size_t)(kp * 8 + j) * NNV + n] = __float2half_rn(((float)w - z) * s);
        }
    }
}

// ---------------------------------------------------------------------------
// GEMM: C = xh @ Wd + bias.  Plain fp16 GEMM, fp32 accum, no fold.
// CTA tile 64x128, BK=64, 4 warps (2m x 2n), warp tile 32x64.
// NS=3 stages x (A 8K | B 16K) = 73.7 KB smem, regs capped for 3 CTAs/SM
// -> 12 warps/SM resident.
// ---------------------------------------------------------------------------
#define NS 3
#define STG_BYTES 24576
#define SMEM_TOTAL (NS * STG_BYTES)   // 73728

__global__ void __launch_bounds__(128, 3)
gemm_kernel(const float* __restrict__ bias,
            float* __restrict__ C)
{
    extern __shared__ __align__(16) char smem[];
    const uint32_t sb = (uint32_t)__cvta_generic_to_shared(smem);
    const int tid = threadIdx.x, lane = tid & 31, wid = tid >> 5;
    const int wm = wid & 1, wn = wid >> 1;
    const int m0 = blockIdx.y * 64, n0 = blockIdx.x * 128;

    // loader: A 64x64 fp16 (512 x 16B chunks), B 64x128 fp16 (1024 chunks)
    auto load_stage = [&](int kt, int st) {
        uint32_t base = sb + st * STG_BYTES;
#pragma unroll
        for (int j = 0; j < 4; ++j) {
            int q = tid + j * 128;
            int r = q >> 3, c = q & 7;
            uint32_t so = base + (uint32_t)(r * 8 + (c ^ (r & 7))) * 16;
            cpa16(so, g_xh + (size_t)(m0 + r) * KKV + kt * 64 + c * 8);
        }
#pragma unroll
        for (int j = 0; j < 8; ++j) {
            int q = tid + j * 128;
            int r = q >> 4, c = q & 15;
            uint32_t so = base + 8192 + (uint32_t)(r * 16 + (c ^ (r & 7))) * 16;
            cpa16(so, g_wd + (size_t)(kt * 64 + r) * NNV + n0 + c * 8);
        }
    };

    // prefill 2 stages
    load_stage(0, 0); CP_COMMIT();
    load_stage(1, 1); CP_COMMIT();

    // ldmatrix address precompute
    const int lane_r = lane & 15, chh = lane >> 4;
    uint32_t arow[2], axr[2];
#pragma unroll
    for (int t = 0; t < 2; ++t) {
        int r = wm * 32 + t * 16 + lane_r;
        arow[t] = (uint32_t)r * 128;            // 128 B per A row
        axr[t]  = (uint32_t)(r & 7);
    }
    const uint32_t xb = (uint32_t)(lane_r & 7);
    uint32_t bcol[4];
#pragma unroll
    for (int bb = 0; bb < 4; ++bb)
        bcol[bb] = (uint32_t)(wn * 8 + (((uint32_t)(bb * 2 + chh)) ^ xb)) * 16;
    uint32_t boff[4];
#pragma unroll
    for (int ks = 0; ks < 4; ++ks)
        boff[ks] = (uint32_t)(ks * 16 + lane_r) * 256;   // 256 B per B row

    float accM[2][8][4];
#pragma unroll
    for (int t = 0; t < 2; ++t)
#pragma unroll
        for (int nt = 0; nt < 8; ++nt)
#pragma unroll
            for (int i = 0; i < 4; ++i) accM[t][nt][i] = 0.f;

    int st = 0, stn = 2;   // rotating stage indices: current, next-to-load
    for (int kt = 0; kt < 64; ++kt) {
        CP_WAIT1();
        __syncthreads();

        const uint32_t Ab = sb + st * STG_BYTES;
        const uint32_t Bb = Ab + 8192;

        if (kt + 2 < 64) load_stage(kt + 2, stn);
        CP_COMMIT();

#pragma unroll
        for (int ks = 0; ks < 4; ++ks) {
            uint32_t af[2][4], bfr[4][4];
#pragma unroll
            for (int t = 0; t < 2; ++t) {
                uint32_t co = ((uint32_t)(ks * 2 + chh) ^ axr[t]) * 16;
                ldsm4(af[t], Ab + arow[t] + co);
            }
#pragma unroll
            for (int bb = 0; bb < 4; ++bb)
                ldsm4t(bfr[bb], Bb + boff[ks] + bcol[bb]);
#pragma unroll
            for (int t = 0; t < 2; ++t)
#pragma unroll
                for (int nt = 0; nt < 8; ++nt)
                    mma_f16(accM[t][nt], af[t], &bfr[nt >> 1][(nt & 1) * 2]);
        }

        st  = (st  == NS - 1) ? 0 : st + 1;
        stn = (stn == NS - 1) ? 0 : stn + 1;
    }

    // epilogue
#pragma unroll
    for (int t = 0; t < 2; ++t) {
        int row0 = m0 + wm * 32 + t * 16 + (lane >> 2);
#pragma unroll
        for (int nt = 0; nt < 8; ++nt) {
            int col = n0 + wn * 64 + nt * 8 + (lane & 3) * 2;
            float2 b = *(const float2*)(bias + col);
            float2 o0, o1;
            o0.x = accM[t][nt][0] + b.x;  o0.y = accM[t][nt][1] + b.y;
            o1.x = accM[t][nt][2] + b.x;  o1.y = accM[t][nt][3] + b.y;
            *(float2*)(C + (size_t)row0 * NNV + col)       = o0;
            *(float2*)(C + (size_t)(row0 + 8) * NNV + col) = o1;
        }
    }
}

// ---------------------------------------------------------------------------
// Host. Inputs: x, scales, zero_points, bias, qweight
// ---------------------------------------------------------------------------
extern "C" void kernel_launch(void* const* d_in, const int* in_sizes, int n_in,
                              void* d_out, int out_size)
{
    const float* x      = (const float*)d_in[0];
    const float* scales = (const float*)d_in[1];
    const float* zp     = (const float*)d_in[2];
    const float* bias   = (const float*)d_in[3];
    const int*   qw     = (const int*)d_in[4];
    float*       out    = (float*)d_out;

    prep_kernel<<<16384, 256>>>((const float4*)x, qw, zp, scales);

    static bool attr_set = false;
    if (!attr_set) {
        cudaFuncSetAttribute(gemm_kernel, cudaFuncAttributeMaxDynamicSharedMemorySize, SMEM_TOTAL);
        attr_set = true;
    }
    gemm_kernel<<<dim3(NNV / 128, MMV / 64), 128, SMEM_TOTAL>>>(bias, out);
}